// round 2
// baseline (speedup 1.0000x reference)
#include <cuda_runtime.h>
#include <cuda_bf16.h>

// Align2D: bilinear warp (grid_sample, border padding) of x[8,64,512,512]
// by flow[8,2,512,512]. Output = concat(x_warp flattened, flow flattened).
//
// One thread per (b, y, x) pixel: compute 4 tap indices + weights once,
// loop over C=64 channels (amortizes flow read + address math 64x).

#define BB 8
#define CC 64
#define HH 512
#define WW 512
#define HWP (HH * WW)

__global__ __launch_bounds__(256) void align2d_warp_kernel(
    const float* __restrict__ x,
    const float* __restrict__ flow,
    float* __restrict__ out)
{
    int pix = blockIdx.x * blockDim.x + threadIdx.x;   // 0 .. B*H*W-1
    if (pix >= BB * HWP) return;

    int b = pix >> 18;           // / HWP (262144 = 2^18)
    int p = pix & (HWP - 1);     // y*W + x
    int yi = p >> 9;             // / WW
    int xi = p & (WW - 1);

    // flow[b, 0, y, x] and flow[b, 1, y, x]
    const float* fp = flow + (size_t)b * 2 * HWP + p;
    float fx = __ldg(fp);
    float fy = __ldg(fp + HWP);

    // clip to border (matches reference exactly)
    float px = fminf(fmaxf((float)xi + fx, 0.0f), (float)(WW - 1));
    float py = fminf(fmaxf((float)yi + fy, 0.0f), (float)(HH - 1));

    float x0f = floorf(px);
    float y0f = floorf(py);
    float wx = px - x0f;
    float wy = py - y0f;

    int x0 = (int)x0f;                 // already in [0, W-1] after clip
    int y0 = (int)y0f;
    int x1 = min(x0 + 1, WW - 1);
    int y1 = min(y0 + 1, HH - 1);

    int i00 = y0 * WW + x0;
    int i01 = y0 * WW + x1;
    int i10 = y1 * WW + x0;
    int i11 = y1 * WW + x1;

    float omwx = 1.0f - wx;
    float omwy = 1.0f - wy;
    float w00 = omwx * omwy;
    float w01 = wx * omwy;
    float w10 = omwx * wy;
    float w11 = wx * wy;

    const float* xb = x   + (size_t)b * CC * HWP;
    float*       ob = out + (size_t)b * CC * HWP + p;

    #pragma unroll 8
    for (int c = 0; c < CC; c++) {
        const float* xc = xb + (size_t)c * HWP;
        float v00 = __ldg(xc + i00);
        float v01 = __ldg(xc + i01);
        float v10 = __ldg(xc + i10);
        float v11 = __ldg(xc + i11);
        float v = fmaf(v00, w00, fmaf(v01, w01, fmaf(v10, w10, v11 * w11)));
        ob[(size_t)c * HWP] = v;
    }
}

extern "C" void kernel_launch(void* const* d_in, const int* in_sizes, int n_in,
                              void* d_out, int out_size)
{
    const float* x    = (const float*)d_in[0];
    const float* flow = (const float*)d_in[1];
    float*       out  = (float*)d_out;

    int npix = BB * HWP;                    // 2,097,152
    int threads = 256;
    int blocks = (npix + threads - 1) / threads;
    align2d_warp_kernel<<<blocks, threads>>>(x, flow, out);

    // flow passthrough: second output component appended after warp output
    size_t warp_elems = (size_t)BB * CC * HWP;
    size_t flow_bytes = (size_t)BB * 2 * HWP * sizeof(float);
    cudaMemcpyAsync(out + warp_elems, flow, flow_bytes,
                    cudaMemcpyDeviceToDevice);
}